// round 4
// baseline (speedup 1.0000x reference)
#include <cuda_runtime.h>

// Problem constants (fixed by setup_inputs)
#define BATCH   16
#define CHAN    4
#define H_IN    128
#define W_IN    240
#define MAXD    24
#define H_OUT   1024
#define W_OUT   1920
#define W4      (W_OUT / 4)     // 480
#define TILE    4               // input rows per block
#define NROWS   (TILE + 1)      // with halo
#define NTILES  (H_IN / TILE)   // 32
#define NTHREADS 256

// ---------------------------------------------------------------------------
// Fused kernel, one block per (batch, 4-input-row tile). Grid = 16*32 = 512.
//  Phase A: stage 5 rows (l+r, channel-packed float4) in ONE pass, compute
//           5 pred rows (cost volume + softmax expectation) -> smem.
//  Phase B: register-resident separable bilinear upsample: each thread owns
//           8 contiguous output pixels; x-geometry hoisted out of row loop;
//           prow values live in registers per input-row-group.
// ---------------------------------------------------------------------------
__global__ __launch_bounds__(NTHREADS, 4) void fused_kernel(
    const float* __restrict__ fl, const float* __restrict__ fr,
    float* __restrict__ out)
{
    const int blk = blockIdx.x;          // b*NTILES + ty
    const int b  = blk >> 5;
    const int ty = blk & (NTILES - 1);
    const int base_y = ty * TILE;

    __shared__ float4 sl4[NROWS][W_IN];
    __shared__ float4 sr4[NROWS][W_IN];
    __shared__ float  prow[NROWS][W_IN + 1];

    // ---- Phase A1: stage all 5 rows (l + r, 4 channels), one pass ----
    for (int i = threadIdx.x; i < 2 * NROWS * CHAN * W_IN; i += NTHREADS) {
        const int x  = i % W_IN;
        const int t  = i / W_IN;        // 0..39
        const int c  = t & 3;
        const int ri = t >> 2;          // 0..9
        const int r  = ri >> 1;
        const int img = ri & 1;
        const int yy = min(base_y + r, H_IN - 1);
        const size_t off = (((size_t)b * CHAN + c) * H_IN + yy) * W_IN + x;
        const float v = img ? fr[off] : fl[off];
        float* dst = img ? (float*)&sr4[r][x] : (float*)&sl4[r][x];
        dst[c] = v;
    }
    __syncthreads();

    // ---- Phase A2: disparity prediction, 5 rows x 240 px, strided ----
    for (int i = threadIdx.x; i < NROWS * W_IN; i += NTHREADS) {
        const int r = i / W_IN;
        const int x = i - r * W_IN;
        const float4 L = sl4[r][x];
        const float absl = fabsf(L.x) + fabsf(L.y) + fabsf(L.z) + fabsf(L.w);

        float num = 0.0f, den = 0.0f;
#pragma unroll
        for (int d = 0; d < MAXD; d++) {
            const int xs = x - d;
            float c;
            if (xs >= 0) {
                const float4 R = sr4[r][xs];
                c = fabsf(L.x - R.x) + fabsf(L.y - R.y)
                  + fabsf(L.z - R.z) + fabsf(L.w - R.w);
            } else {
                c = absl;                     // zero padding
            }
            const float e = __expf(-c);       // softmax(-cost), unshifted
            den += e;
            num += (float)d * e;
        }
        prow[r][x] = (num / den) * 8.0f;      // * (1024/128)
    }
    __syncthreads();
    if (threadIdx.x < NROWS)
        prow[threadIdx.x][W_IN] = prow[threadIdx.x][W_IN - 1];  // x-pad
    __syncthreads();

    // ---- Phase B: register-resident bilinear upsample ----
    const float xsc = 239.0f / 1919.0f;
    const float ysc = 127.0f / 1023.0f;
    const int t = threadIdx.x;
    if (t < 240) {
        const int ox0 = t * 8;                       // 8 contiguous out px
        const int q = (int)((float)ox0 * xsc);       // base input cell
        float wx[8];
        bool  hi[8];
#pragma unroll
        for (int k = 0; k < 8; k++) {
            const float xf = (float)(ox0 + k) * xsc;
            const int x0 = (int)xf;
            wx[k] = xf - (float)x0;
            hi[k] = (x0 > q);                        // pixel in cell q+1?
        }

        float4* __restrict__ out4 =
            (float4*)out + (size_t)b * H_OUT * W4 + t * 2;

#pragma unroll
        for (int r = 0; r < TILE; r++) {
            const int yr = base_y + r;
            const int oys = (yr * (H_OUT - 1) + (H_IN - 2)) / (H_IN - 1);
            const int oye = min(H_OUT - 1,
                ((yr + 1) * (H_OUT - 1) + (H_IN - 2)) / (H_IN - 1) - 1);

            // register-resident prow window for this input-row pair
            const float p00 = prow[r][q],     p01 = prow[r][q + 1],
                        p02 = prow[r][q + 2];
            const float D0 = prow[r + 1][q]     - p00;
            const float D1 = prow[r + 1][q + 1] - p01;
            const float D2 = prow[r + 1][q + 2] - p02;

            for (int oy = oys; oy <= oye; oy++) {
                const float wy = (float)oy * ysc - (float)yr;
                const float v0 = p00 + wy * D0;      // y-lerp (3 FMA)
                const float v1 = p01 + wy * D1;
                const float v2 = p02 + wy * D2;
                const float d01 = v1 - v0;
                const float d12 = v2 - v1;

                float4 o0, o1;
#pragma unroll
                for (int k = 0; k < 8; k++) {
                    const float base = hi[k] ? v1 : v0;
                    const float del  = hi[k] ? d12 : d01;
                    const float val  = base + wx[k] * del;
                    if (k < 4) ((float*)&o0)[k]     = val;
                    else       ((float*)&o1)[k - 4] = val;
                }
                float4* __restrict__ orow = out4 + (size_t)oy * W4;
                orow[0] = o0;
                orow[1] = o1;
            }
        }
    }
}

extern "C" void kernel_launch(void* const* d_in, const int* in_sizes, int n_in,
                              void* d_out, int out_size)
{
    const float* feat_l = (const float*)d_in[0];
    const float* feat_r = (const float*)d_in[1];
    float* out = (float*)d_out;

    fused_kernel<<<BATCH * NTILES, NTHREADS>>>(feat_l, feat_r, out);
}